// round 13
// baseline (speedup 1.0000x reference)
#include <cuda_runtime.h>
#include <cuda_fp16.h>
#include <cstdint>

// ---------------------------------------------------------------------------
// BayesKerasDense TT-dense: y = relu(x @ M + b)
// R10 profile: GEMM was F2F(cvt)-bound; prep ~200us dominated by scalar FFMA.
// R11 fix (this round): k_build_T3 needed ALL of core2 = 16384 floats (64KB)
//   in smem but allocated 16KB -> OOB read -> illegal access. Now uses 64KB
//   dynamic smem with the opt-in attribute.
// GEMM: K=64 f16 mma chain per promote (cvt halves vs R10) -> tensor-bound.
// Prep: packed fma.rn.f32x2 contractions (fp32 precision, 2x rate).
// ---------------------------------------------------------------------------

#define NF 4096

__device__ float  g_T2[64 * 64 * 16];          // 256 KB
__device__ float  g_T3[512 * 512 * 16];        // 16.8 MB
__device__ __half g_Mt[(size_t)NF * NF];       // 32 MB, [n][k]
__device__ __half g_Xh[(size_t)NF * NF];       // 32 MB, [m][k]

// ---------------- f32x2 helpers --------------------------------------------

__device__ __forceinline__ unsigned long long pk2(float v) {
    unsigned long long r;
    asm("mov.b64 %0, {%1, %1};" : "=l"(r) : "f"(v));
    return r;
}
__device__ __forceinline__ void fma2(unsigned long long& d, unsigned long long a,
                                     unsigned long long b) {
    asm("fma.rn.f32x2 %0, %1, %2, %0;" : "+l"(d) : "l"(a), "l"(b));
}
__device__ __forceinline__ float2 upk(unsigned long long v) {
    float2 f;
    asm("mov.b64 {%0, %1}, %2;" : "=f"(f.x), "=f"(f.y) : "l"(v));
    return f;
}

// ---------------- stage 1: prep kernels ------------------------------------

// fused: blocks [0,256) build T2; blocks [256, 16640) convert x -> fp16
__global__ void k_prep0(const float* __restrict__ c0, const float* __restrict__ c1,
                        const float4* __restrict__ x4) {
    if (blockIdx.x < 256) {
        int idx = blockIdx.x * 256 + threadIdx.x;
        int r2 = idx & 15;
        int q2 = (idx >> 4) & 63;
        int p2 = idx >> 10;
        int a0 = p2 >> 3, a1 = p2 & 7;
        int b0 = q2 >> 3, b1 = q2 & 7;
        float s = 0.f;
#pragma unroll
        for (int r1 = 0; r1 < 16; ++r1)
            s += c0[(a0 * 8 + b0) * 16 + r1] * c1[((r1 * 8 + a1) * 8 + b1) * 16 + r2];
        g_T2[idx] = s;
    } else {
        int idx = (blockIdx.x - 256) * 256 + threadIdx.x;
        float4 v = x4[idx];
        __half2* o = (__half2*)g_Xh;
        o[idx * 2 + 0] = __floats2half2_rn(v.x, v.y);
        o[idx * 2 + 1] = __floats2half2_rn(v.z, v.w);
    }
}

// T3[p3=(p2,a2)][q3=(q2,b2)][r3] = sum_r2 T2[p2,q2,r2] * c2[r2,a2,b2,r3]
// block = one (p2,q2); thread = (a2,b2,r3quad); f32x2 packed over r3 pairs.
// c2 = 16*8*8*16 = 16384 floats = 64KB -> DYNAMIC smem (R11 had 16KB: OOB).
#define T3_SMEM (16384 * 4)
__global__ void k_build_T3(const float* __restrict__ c2) {
    extern __shared__ float c2s[];                 // 64 KB dynamic
    __shared__ unsigned long long t2p[16];
    const int tid = threadIdx.x;
    const int p2 = blockIdx.x >> 6, q2 = blockIdx.x & 63;
    for (int i = tid; i < 4096; i += 256)
        *(float4*)(c2s + i * 4) = *(const float4*)(c2 + i * 4);
    if (tid < 16) t2p[tid] = pk2(g_T2[((p2 << 6) + q2) * 16 + tid]);
    __syncthreads();

    const int a2 = tid >> 5, b2 = (tid >> 2) & 7, r3q = tid & 3;
    unsigned long long s0 = 0ull, s1 = 0ull;
#pragma unroll
    for (int r2 = 0; r2 < 16; ++r2) {
        unsigned long long tt = t2p[r2];
        const unsigned long long* cp =
            (const unsigned long long*)&c2s[((r2 * 8 + a2) * 8 + b2) * 16 + r3q * 4];
        fma2(s0, tt, cp[0]);
        fma2(s1, tt, cp[1]);
    }
    float2 f0 = upk(s0), f1 = upk(s1);
    const int p3 = p2 * 8 + a2, q3 = q2 * 8 + b2;
    float4 v;
    v.x = f0.x; v.y = f0.y; v.z = f1.x; v.w = f1.y;
    *(float4*)(g_T3 + ((((size_t)p3 << 9) + q3) << 4) + r3q * 4) = v;
}

// Mt[b=(q3,b3)][a=(p3,a3)] = sum_r3 T3[p3,q3,r3] * c3[r3,a3,b3]
// thread = (q3, a): loads one T3 row (16 floats), emits 8 b3 outputs.
// c3 = 16*8*8 = 1024 floats = 4KB static smem (correct size).
__global__ void k_build_M(const float* __restrict__ c3) {
    __shared__ float c3s[1024];
    for (int i = threadIdx.x; i < 1024; i += 256) c3s[i] = c3[i];
    __syncthreads();

    const int idx = blockIdx.x * 256 + threadIdx.x;   // 512*4096 = 2M
    const int a = idx & (NF - 1);
    const int q3 = idx >> 12;
    const int a3 = a & 7, p3 = a >> 3;

    const float4* t4 = (const float4*)(g_T3 + ((((size_t)p3 << 9) + q3) << 4));
    float t[16];
    *(float4*)(t + 0)  = t4[0];
    *(float4*)(t + 4)  = t4[1];
    *(float4*)(t + 8)  = t4[2];
    *(float4*)(t + 12) = t4[3];

    unsigned long long s0 = 0ull, s1 = 0ull, s2 = 0ull, s3 = 0ull;
#pragma unroll
    for (int r3 = 0; r3 < 16; ++r3) {
        unsigned long long tt = pk2(t[r3]);
        const unsigned long long* cp =
            (const unsigned long long*)&c3s[(r3 * 8 + a3) * 8];
        fma2(s0, tt, cp[0]);
        fma2(s1, tt, cp[1]);
        fma2(s2, tt, cp[2]);
        fma2(s3, tt, cp[3]);
    }
    float2 f0 = upk(s0), f1 = upk(s1), f2 = upk(s2), f3 = upk(s3);
    __half* o = g_Mt + (size_t)(q3 * 8) * NF + a;
    o[0 * NF] = __float2half(f0.x);
    o[1 * NF] = __float2half(f0.y);
    o[2 * NF] = __float2half(f1.x);
    o[3 * NF] = __float2half(f1.y);
    o[4 * NF] = __float2half(f2.x);
    o[5 * NF] = __float2half(f2.y);
    o[6 * NF] = __float2half(f3.x);
    o[7 * NF] = __float2half(f3.y);
}

__global__ void k_nop() {}   // keeps ncu's capture slot aligned on k_gemm

// ---------------- stage 2: fp16 HMMA GEMM ----------------------------------

#define BM 128
#define BN 256
#define BK 64
#define KT (NF / BK)                 // 64
#define A_BYTES (BM * 128)           // 16 KB
#define B_BYTES (BN * 128)           // 32 KB
#define STAGE_BYTES (A_BYTES + B_BYTES)   // 48 KB
#define STAGES 4
#define SMEM_TOTAL (STAGES * STAGE_BYTES) // 192 KB
#define NTHR 512

__device__ __forceinline__ uint32_t sw128(uint32_t off) {
    return off ^ ((off >> 3) & 0x70);
}
__device__ __forceinline__ void cp_async16(uint32_t smem, const void* gmem) {
    asm volatile("cp.async.cg.shared.global [%0], [%1], 16;\n" :: "r"(smem), "l"(gmem));
}
__device__ __forceinline__ void cp_commit() {
    asm volatile("cp.async.commit_group;\n" ::: "memory");
}
__device__ __forceinline__ void ldmatrix_x4(uint32_t* r, uint32_t s) {
    asm volatile("ldmatrix.sync.aligned.m8n8.x4.shared.b16 {%0,%1,%2,%3}, [%4];\n"
                 : "=r"(r[0]), "=r"(r[1]), "=r"(r[2]), "=r"(r[3]) : "r"(s));
}
__device__ __forceinline__ void mma_h_z(uint32_t* d, const uint32_t* a,
                                        const uint32_t* b, uint32_t z) {
    asm volatile("mma.sync.aligned.m16n8k16.row.col.f16.f16.f16.f16 "
                 "{%0,%1}, {%2,%3,%4,%5}, {%6,%7}, {%8,%8};\n"
                 : "=r"(d[0]), "=r"(d[1])
                 : "r"(a[0]), "r"(a[1]), "r"(a[2]), "r"(a[3]),
                   "r"(b[0]), "r"(b[1]), "r"(z));
}
__device__ __forceinline__ void mma_h(uint32_t* d, const uint32_t* a,
                                      const uint32_t* b) {
    asm volatile("mma.sync.aligned.m16n8k16.row.col.f16.f16.f16.f16 "
                 "{%0,%1}, {%2,%3,%4,%5}, {%6,%7}, {%0,%1};\n"
                 : "+r"(d[0]), "+r"(d[1])
                 : "r"(a[0]), "r"(a[1]), "r"(a[2]), "r"(a[3]),
                   "r"(b[0]), "r"(b[1]));
}

__global__ __launch_bounds__(NTHR, 1) void k_gemm(const float* __restrict__ bias,
                                                  float* __restrict__ out) {
    extern __shared__ char smem[];
    uint32_t sb;
    asm("{ .reg .u64 t; cvta.to.shared.u64 t, %1; cvt.u32.u64 %0, t; }"
        : "=r"(sb) : "l"((void*)smem));

    const int tid  = threadIdx.x;
    const int lane = tid & 31;
    const int warp = tid >> 5;      // 0..15
    const int warpM = warp & 3;     // 4 slabs of 32 rows
    const int warpN = warp >> 2;    // 4 slabs of 64 cols
    const int bm = blockIdx.y * BM;
    const int bn = blockIdx.x * BN;

    const __half* Ag = g_Xh;  // [m][k]
    const __half* Bg = g_Mt;  // [n][k]

    float acc[2][8][4];
#pragma unroll
    for (int i = 0; i < 2; i++)
#pragma unroll
        for (int j = 0; j < 8; j++)
#pragma unroll
            for (int k = 0; k < 4; k++) acc[i][j][k] = 0.f;

    uint32_t zero = 0u;

    // Pre-swizzled bases (bits 5-6 clear pre-swizzle); k-slice offset via XOR.
    uint32_t aSw[2];
#pragma unroll
    for (int mi = 0; mi < 2; ++mi) {
        uint32_t off = (uint32_t)(warpM * 32 + mi * 16 + (lane & 15)) * 128
                     + (uint32_t)(lane >> 4) * 16;
        aSw[mi] = sw128(off);
    }
    uint32_t bSw[4];
#pragma unroll
    for (int p = 0; p < 4; ++p) {
        uint32_t row = (uint32_t)(warpN * 64 + p * 16 + ((lane & 16) >> 1) + (lane & 7));
        uint32_t off = row * 128 + (uint32_t)(lane & 8) * 2;
        bSw[p] = sw128(off);
    }

    // stage loader: 3072 x 16B chunks (1024 A + 2048 B), 6 per thread
    auto load_stage = [&](int s, int kt) {
        const int kk = kt * BK;
        const uint32_t base = sb + (uint32_t)s * STAGE_BYTES;
#pragma unroll
        for (int i = 0; i < 6; ++i) {
            int cid = tid + i * NTHR;
            if (cid < 1024) {                       // A: 128 rows x 8 chunks
                int r = cid >> 3, c = cid & 7;
                cp_async16(base + sw128((uint32_t)(r * 128 + c * 16)),
                           Ag + (size_t)(bm + r) * NF + kk + c * 8);
            } else {                                // B: 256 rows x 8 chunks
                int cid2 = cid - 1024;
                int r = cid2 >> 3, c = cid2 & 7;
                cp_async16(base + A_BYTES + sw128((uint32_t)(r * 128 + c * 16)),
                           Bg + (size_t)(bn + r) * NF + kk + c * 8);
            }
        }
        cp_commit();
    };

    load_stage(0, 0);
    load_stage(1, 1);
    load_stage(2, 2);

    for (int kt = 0; kt < KT; ++kt) {
        asm volatile("cp.async.wait_group 2;\n" ::: "memory");
        __syncthreads();
        if (kt + 3 < KT) load_stage((kt + 3) & 3, kt + 3);
        else cp_commit();

        const uint32_t stA = sb + (uint32_t)(kt & 3) * STAGE_BYTES;
        const uint32_t stB = stA + A_BYTES;
#pragma unroll
        for (int mi = 0; mi < 2; ++mi) {
            uint32_t af[4][4];                      // 4 k-slices of this 16-row band
#pragma unroll
            for (int k = 0; k < 4; ++k)
                ldmatrix_x4(af[k], stA + (aSw[mi] ^ ((uint32_t)k << 5)));
#pragma unroll
            for (int p = 0; p < 4; ++p) {
                uint32_t bf[4][4];
#pragma unroll
                for (int k = 0; k < 4; ++k)
                    ldmatrix_x4(bf[k], stB + (bSw[p] ^ ((uint32_t)k << 5)));
#pragma unroll
                for (int h = 0; h < 2; ++h) {
                    // K=64 chain entirely in f16, then one promote
                    uint32_t c2[2];
                    mma_h_z(c2, af[0], &bf[0][h * 2], zero);
                    mma_h(c2, af[1], &bf[1][h * 2]);
                    mma_h(c2, af[2], &bf[2][h * 2]);
                    mma_h(c2, af[3], &bf[3][h * 2]);
                    const int ni = p * 2 + h;
                    float2 f0 = __half22float2(*reinterpret_cast<__half2*>(&c2[0]));
                    float2 f1 = __half22float2(*reinterpret_cast<__half2*>(&c2[1]));
                    acc[mi][ni][0] += f0.x;
                    acc[mi][ni][1] += f0.y;
                    acc[mi][ni][2] += f1.x;
                    acc[mi][ni][3] += f1.y;
                }
            }
        }
    }

    // epilogue: relu(acc + bias), fp32 out
#pragma unroll
    for (int mi = 0; mi < 2; ++mi) {
#pragma unroll
        for (int ni = 0; ni < 8; ++ni) {
            int row = bm + warpM * 32 + mi * 16 + (lane >> 2);
            int col = bn + warpN * 64 + ni * 8 + (lane & 3) * 2;
            float b0 = __ldg(bias + col), b1 = __ldg(bias + col + 1);
            float2 v0, v1;
            v0.x = fmaxf(acc[mi][ni][0] + b0, 0.f);
            v0.y = fmaxf(acc[mi][ni][1] + b1, 0.f);
            v1.x = fmaxf(acc[mi][ni][2] + b0, 0.f);
            v1.y = fmaxf(acc[mi][ni][3] + b1, 0.f);
            *(float2*)(out + (size_t)row * NF + col) = v0;
            *(float2*)(out + (size_t)(row + 8) * NF + col) = v1;
        }
    }
}

// ---------------------------------------------------------------------------

extern "C" void kernel_launch(void* const* d_in, const int* in_sizes, int n_in,
                              void* d_out, int out_size) {
    const float* x  = (const float*)d_in[0];
    const float* c0 = (const float*)d_in[1];
    const float* c1 = (const float*)d_in[2];
    const float* c2 = (const float*)d_in[3];
    const float* c3 = (const float*)d_in[4];
    const float* bv = (const float*)d_in[5];
    float* out = (float*)d_out;

    static bool attr_done = false;
    if (!attr_done) {
        cudaFuncSetAttribute(k_gemm, cudaFuncAttributeMaxDynamicSharedMemorySize,
                             SMEM_TOTAL);
        cudaFuncSetAttribute(k_build_T3, cudaFuncAttributeMaxDynamicSharedMemorySize,
                             T3_SMEM);
        attr_done = true;
    }

    k_prep0<<<16640, 256>>>(c0, c1, (const float4*)x);   // T2 + x->fp16
    k_build_T3<<<4096, 256, T3_SMEM>>>(c2);
    k_build_M<<<8192, 256>>>(c3);

    dim3 grid(NF / BN, NF / BM);  // (16, 32)
    k_gemm<<<grid, NTHR, SMEM_TOTAL>>>(bv, out);
    k_nop<<<1, 32>>>();
}

// round 16
// speedup vs baseline: 1.2158x; 1.2158x over previous
#include <cuda_runtime.h>
#include <cuda_fp16.h>
#include <cstdint>

// ---------------------------------------------------------------------------
// BayesKerasDense TT-dense: y = relu(x @ M + b)
// R13 lesson: K=64 f16 chain halved cvt (fma 24.8->10.8%) but the loop order
// reloaded B frags per mi band: 40 ldmatrix/kt/warp -> crossbar 2560 cyc/kt
// > tensor 2048 -> smem-bound (L1 52%). R14: hoist A for both mi bands, load
// each B frag once -> 24 ldmatrix/kt/warp (crossbar 1536 < tensor 2048).
// Prep: packed fma.rn.f32x2 contractions (fp32 precision, 2x rate).
// ---------------------------------------------------------------------------

#define NF 4096

__device__ float  g_T2[64 * 64 * 16];          // 256 KB
__device__ float  g_T3[512 * 512 * 16];        // 16.8 MB
__device__ __half g_Mt[(size_t)NF * NF];       // 32 MB, [n][k]
__device__ __half g_Xh[(size_t)NF * NF];       // 32 MB, [m][k]

// ---------------- f32x2 helpers --------------------------------------------

__device__ __forceinline__ unsigned long long pk2(float v) {
    unsigned long long r;
    asm("mov.b64 %0, {%1, %1};" : "=l"(r) : "f"(v));
    return r;
}
__device__ __forceinline__ void fma2(unsigned long long& d, unsigned long long a,
                                     unsigned long long b) {
    asm("fma.rn.f32x2 %0, %1, %2, %0;" : "+l"(d) : "l"(a), "l"(b));
}
__device__ __forceinline__ float2 upk(unsigned long long v) {
    float2 f;
    asm("mov.b64 {%0, %1}, %2;" : "=f"(f.x), "=f"(f.y) : "l"(v));
    return f;
}

// ---------------- stage 1: prep kernels ------------------------------------

// fused: blocks [0,256) build T2; blocks [256, 16640) convert x -> fp16
__global__ void k_prep0(const float* __restrict__ c0, const float* __restrict__ c1,
                        const float4* __restrict__ x4) {
    if (blockIdx.x < 256) {
        int idx = blockIdx.x * 256 + threadIdx.x;
        int r2 = idx & 15;
        int q2 = (idx >> 4) & 63;
        int p2 = idx >> 10;
        int a0 = p2 >> 3, a1 = p2 & 7;
        int b0 = q2 >> 3, b1 = q2 & 7;
        float s = 0.f;
#pragma unroll
        for (int r1 = 0; r1 < 16; ++r1)
            s += c0[(a0 * 8 + b0) * 16 + r1] * c1[((r1 * 8 + a1) * 8 + b1) * 16 + r2];
        g_T2[idx] = s;
    } else {
        int idx = (blockIdx.x - 256) * 256 + threadIdx.x;
        float4 v = x4[idx];
        __half2* o = (__half2*)g_Xh;
        o[idx * 2 + 0] = __floats2half2_rn(v.x, v.y);
        o[idx * 2 + 1] = __floats2half2_rn(v.z, v.w);
    }
}

// T3[p3=(p2,a2)][q3=(q2,b2)][r3] = sum_r2 T2[p2,q2,r2] * c2[r2,a2,b2,r3]
// c2 = 16384 floats = 64KB dynamic smem.
#define T3_SMEM (16384 * 4)
__global__ void k_build_T3(const float* __restrict__ c2) {
    extern __shared__ float c2s[];
    __shared__ unsigned long long t2p[16];
    const int tid = threadIdx.x;
    const int p2 = blockIdx.x >> 6, q2 = blockIdx.x & 63;
    for (int i = tid; i < 4096; i += 256)
        *(float4*)(c2s + i * 4) = *(const float4*)(c2 + i * 4);
    if (tid < 16) t2p[tid] = pk2(g_T2[((p2 << 6) + q2) * 16 + tid]);
    __syncthreads();

    const int a2 = tid >> 5, b2 = (tid >> 2) & 7, r3q = tid & 3;
    unsigned long long s0 = 0ull, s1 = 0ull;
#pragma unroll
    for (int r2 = 0; r2 < 16; ++r2) {
        unsigned long long tt = t2p[r2];
        const unsigned long long* cp =
            (const unsigned long long*)&c2s[((r2 * 8 + a2) * 8 + b2) * 16 + r3q * 4];
        fma2(s0, tt, cp[0]);
        fma2(s1, tt, cp[1]);
    }
    float2 f0 = upk(s0), f1 = upk(s1);
    const int p3 = p2 * 8 + a2, q3 = q2 * 8 + b2;
    float4 v;
    v.x = f0.x; v.y = f0.y; v.z = f1.x; v.w = f1.y;
    *(float4*)(g_T3 + ((((size_t)p3 << 9) + q3) << 4) + r3q * 4) = v;
}

// Mt[b=(q3,b3)][a=(p3,a3)] = sum_r3 T3[p3,q3,r3] * c3[r3,a3,b3]
__global__ void k_build_M(const float* __restrict__ c3) {
    __shared__ float c3s[1024];
    for (int i = threadIdx.x; i < 1024; i += 256) c3s[i] = c3[i];
    __syncthreads();

    const int idx = blockIdx.x * 256 + threadIdx.x;   // 512*4096 = 2M
    const int a = idx & (NF - 1);
    const int q3 = idx >> 12;
    const int a3 = a & 7, p3 = a >> 3;

    const float4* t4 = (const float4*)(g_T3 + ((((size_t)p3 << 9) + q3) << 4));
    float t[16];
    *(float4*)(t + 0)  = t4[0];
    *(float4*)(t + 4)  = t4[1];
    *(float4*)(t + 8)  = t4[2];
    *(float4*)(t + 12) = t4[3];

    unsigned long long s0 = 0ull, s1 = 0ull, s2 = 0ull, s3 = 0ull;
#pragma unroll
    for (int r3 = 0; r3 < 16; ++r3) {
        unsigned long long tt = pk2(t[r3]);
        const unsigned long long* cp =
            (const unsigned long long*)&c3s[(r3 * 8 + a3) * 8];
        fma2(s0, tt, cp[0]);
        fma2(s1, tt, cp[1]);
        fma2(s2, tt, cp[2]);
        fma2(s3, tt, cp[3]);
    }
    float2 f0 = upk(s0), f1 = upk(s1), f2 = upk(s2), f3 = upk(s3);
    __half* o = g_Mt + (size_t)(q3 * 8) * NF + a;
    o[0 * NF] = __float2half(f0.x);
    o[1 * NF] = __float2half(f0.y);
    o[2 * NF] = __float2half(f1.x);
    o[3 * NF] = __float2half(f1.y);
    o[4 * NF] = __float2half(f2.x);
    o[5 * NF] = __float2half(f2.y);
    o[6 * NF] = __float2half(f3.x);
    o[7 * NF] = __float2half(f3.y);
}

__global__ void k_nop() {}   // keeps ncu's capture slot aligned on k_gemm

// ---------------- stage 2: fp16 HMMA GEMM ----------------------------------

#define BM 128
#define BN 256
#define BK 64
#define KT (NF / BK)                 // 64
#define A_BYTES (BM * 128)           // 16 KB
#define B_BYTES (BN * 128)           // 32 KB
#define STAGE_BYTES (A_BYTES + B_BYTES)   // 48 KB
#define STAGES 4
#define SMEM_TOTAL (STAGES * STAGE_BYTES) // 192 KB
#define NTHR 512

__device__ __forceinline__ uint32_t sw128(uint32_t off) {
    return off ^ ((off >> 3) & 0x70);
}
__device__ __forceinline__ void cp_async16(uint32_t smem, const void* gmem) {
    asm volatile("cp.async.cg.shared.global [%0], [%1], 16;\n" :: "r"(smem), "l"(gmem));
}
__device__ __forceinline__ void cp_commit() {
    asm volatile("cp.async.commit_group;\n" ::: "memory");
}
__device__ __forceinline__ void ldmatrix_x4(uint32_t* r, uint32_t s) {
    asm volatile("ldmatrix.sync.aligned.m8n8.x4.shared.b16 {%0,%1,%2,%3}, [%4];\n"
                 : "=r"(r[0]), "=r"(r[1]), "=r"(r[2]), "=r"(r[3]) : "r"(s));
}
__device__ __forceinline__ void mma_h_z(uint32_t* d, const uint32_t* a,
                                        const uint32_t* b, uint32_t z) {
    asm volatile("mma.sync.aligned.m16n8k16.row.col.f16.f16.f16.f16 "
                 "{%0,%1}, {%2,%3,%4,%5}, {%6,%7}, {%8,%8};\n"
                 : "=r"(d[0]), "=r"(d[1])
                 : "r"(a[0]), "r"(a[1]), "r"(a[2]), "r"(a[3]),
                   "r"(b[0]), "r"(b[1]), "r"(z));
}
__device__ __forceinline__ void mma_h(uint32_t* d, const uint32_t* a,
                                      const uint32_t* b) {
    asm volatile("mma.sync.aligned.m16n8k16.row.col.f16.f16.f16.f16 "
                 "{%0,%1}, {%2,%3,%4,%5}, {%6,%7}, {%0,%1};\n"
                 : "+r"(d[0]), "+r"(d[1])
                 : "r"(a[0]), "r"(a[1]), "r"(a[2]), "r"(a[3]),
                   "r"(b[0]), "r"(b[1]));
}

__global__ __launch_bounds__(NTHR, 1) void k_gemm(const float* __restrict__ bias,
                                                  float* __restrict__ out) {
    extern __shared__ char smem[];
    uint32_t sb;
    asm("{ .reg .u64 t; cvta.to.shared.u64 t, %1; cvt.u32.u64 %0, t; }"
        : "=r"(sb) : "l"((void*)smem));

    const int tid  = threadIdx.x;
    const int lane = tid & 31;
    const int warp = tid >> 5;      // 0..15
    const int warpM = warp & 3;     // 4 slabs of 32 rows
    const int warpN = warp >> 2;    // 4 slabs of 64 cols
    const int bm = blockIdx.y * BM;
    const int bn = blockIdx.x * BN;

    const __half* Ag = g_Xh;  // [m][k]
    const __half* Bg = g_Mt;  // [n][k]

    float acc[2][8][4];
#pragma unroll
    for (int i = 0; i < 2; i++)
#pragma unroll
        for (int j = 0; j < 8; j++)
#pragma unroll
            for (int k = 0; k < 4; k++) acc[i][j][k] = 0.f;

    uint32_t zero = 0u;

    // Pre-swizzled bases (bits 5-6 clear pre-swizzle); k-slice offset via XOR.
    uint32_t aSw[2];
#pragma unroll
    for (int mi = 0; mi < 2; ++mi) {
        uint32_t off = (uint32_t)(warpM * 32 + mi * 16 + (lane & 15)) * 128
                     + (uint32_t)(lane >> 4) * 16;
        aSw[mi] = sw128(off);
    }
    uint32_t bSw[4];
#pragma unroll
    for (int p = 0; p < 4; ++p) {
        uint32_t row = (uint32_t)(warpN * 64 + p * 16 + ((lane & 16) >> 1) + (lane & 7));
        uint32_t off = row * 128 + (uint32_t)(lane & 8) * 2;
        bSw[p] = sw128(off);
    }

    // stage loader: 3072 x 16B chunks (1024 A + 2048 B), 6 per thread
    auto load_stage = [&](int s, int kt) {
        const int kk = kt * BK;
        const uint32_t base = sb + (uint32_t)s * STAGE_BYTES;
#pragma unroll
        for (int i = 0; i < 6; ++i) {
            int cid = tid + i * NTHR;
            if (cid < 1024) {                       // A: 128 rows x 8 chunks
                int r = cid >> 3, c = cid & 7;
                cp_async16(base + sw128((uint32_t)(r * 128 + c * 16)),
                           Ag + (size_t)(bm + r) * NF + kk + c * 8);
            } else {                                // B: 256 rows x 8 chunks
                int cid2 = cid - 1024;
                int r = cid2 >> 3, c = cid2 & 7;
                cp_async16(base + A_BYTES + sw128((uint32_t)(r * 128 + c * 16)),
                           Bg + (size_t)(bn + r) * NF + kk + c * 8);
            }
        }
        cp_commit();
    };

    load_stage(0, 0);
    load_stage(1, 1);
    load_stage(2, 2);

    for (int kt = 0; kt < KT; ++kt) {
        asm volatile("cp.async.wait_group 2;\n" ::: "memory");
        __syncthreads();
        if (kt + 3 < KT) load_stage((kt + 3) & 3, kt + 3);
        else cp_commit();

        const uint32_t stA = sb + (uint32_t)(kt & 3) * STAGE_BYTES;
        const uint32_t stB = stA + A_BYTES;

        // All A fragments for both 16-row bands up front: 8 ldmatrix.
        uint32_t af[2][4][4];
#pragma unroll
        for (int mi = 0; mi < 2; ++mi)
#pragma unroll
            for (int k = 0; k < 4; ++k)
                ldmatrix_x4(af[mi][k], stA + (aSw[mi] ^ ((uint32_t)k << 5)));

#pragma unroll
        for (int p = 0; p < 4; ++p) {
            // Each B fragment loaded exactly once: 4 ldmatrix per p.
            uint32_t bf[4][4];
#pragma unroll
            for (int k = 0; k < 4; ++k)
                ldmatrix_x4(bf[k], stB + (bSw[p] ^ ((uint32_t)k << 5)));
#pragma unroll
            for (int mi = 0; mi < 2; ++mi) {
#pragma unroll
                for (int h = 0; h < 2; ++h) {
                    // K=64 chain entirely in f16, then one promote
                    uint32_t c2[2];
                    mma_h_z(c2, af[mi][0], &bf[0][h * 2], zero);
                    mma_h(c2, af[mi][1], &bf[1][h * 2]);
                    mma_h(c2, af[mi][2], &bf[2][h * 2]);
                    mma_h(c2, af[mi][3], &bf[3][h * 2]);
                    const int ni = p * 2 + h;
                    float2 f0 = __half22float2(*reinterpret_cast<__half2*>(&c2[0]));
                    float2 f1 = __half22float2(*reinterpret_cast<__half2*>(&c2[1]));
                    acc[mi][ni][0] += f0.x;
                    acc[mi][ni][1] += f0.y;
                    acc[mi][ni][2] += f1.x;
                    acc[mi][ni][3] += f1.y;
                }
            }
        }
    }

    // epilogue: relu(acc + bias), fp32 out
#pragma unroll
    for (int mi = 0; mi < 2; ++mi) {
#pragma unroll
        for (int ni = 0; ni < 8; ++ni) {
            int row = bm + warpM * 32 + mi * 16 + (lane >> 2);
            int col = bn + warpN * 64 + ni * 8 + (lane & 3) * 2;
            float b0 = __ldg(bias + col), b1 = __ldg(bias + col + 1);
            float2 v0, v1;
            v0.x = fmaxf(acc[mi][ni][0] + b0, 0.f);
            v0.y = fmaxf(acc[mi][ni][1] + b1, 0.f);
            v1.x = fmaxf(acc[mi][ni][2] + b0, 0.f);
            v1.y = fmaxf(acc[mi][ni][3] + b1, 0.f);
            *(float2*)(out + (size_t)row * NF + col) = v0;
            *(float2*)(out + (size_t)(row + 8) * NF + col) = v1;
        }
    }
}

// ---------------------------------------------------------------------------

extern "C" void kernel_launch(void* const* d_in, const int* in_sizes, int n_in,
                              void* d_out, int out_size) {
    const float* x  = (const float*)d_in[0];
    const float* c0 = (const float*)d_in[1];
    const float* c1 = (const float*)d_in[2];
    const float* c2 = (const float*)d_in[3];
    const float* c3 = (const float*)d_in[4];
    const float* bv = (const float*)d_in[5];
    float* out = (float*)d_out;

    static bool attr_done = false;
    if (!attr_done) {
        cudaFuncSetAttribute(k_gemm, cudaFuncAttributeMaxDynamicSharedMemorySize,
                             SMEM_TOTAL);
        cudaFuncSetAttribute(k_build_T3, cudaFuncAttributeMaxDynamicSharedMemorySize,
                             T3_SMEM);
        attr_done = true;
    }

    k_prep0<<<16640, 256>>>(c0, c1, (const float4*)x);   // T2 + x->fp16
    k_build_T3<<<4096, 256, T3_SMEM>>>(c2);
    k_build_M<<<8192, 256>>>(c3);

    dim3 grid(NF / BN, NF / BM);  // (16, 32)
    k_gemm<<<grid, NTHR, SMEM_TOTAL>>>(bv, out);
    k_nop<<<1, 32>>>();
}

// round 17
// speedup vs baseline: 1.2767x; 1.0500x over previous
#include <cuda_runtime.h>
#include <cuda_fp16.h>
#include <cstdint>

// ---------------------------------------------------------------------------
// BayesKerasDense TT-dense: y = relu(x @ M + b)
// R16: tensor busy pinned at ~226us but pipe idle half the time (47.7%),
//   issue 34.2% -> exposed RAW latency of the serial 4-mma f16 chain (1 CTA/SM,
//   4 warps/SMSP cannot cover it; 128-reg cap leaves ptxas no ILP room).
// R17: advance all 4 chains of a p-group (mi x h) in lockstep, stage by
//   stage -> per-chain RAW separated by 3 independent mmas (ILP=4/warp).
// Prep: packed fma.rn.f32x2 contractions.
// ---------------------------------------------------------------------------

#define NF 4096

__device__ float  g_T2[64 * 64 * 16];          // 256 KB
__device__ float  g_T3[512 * 512 * 16];        // 16.8 MB
__device__ __half g_Mt[(size_t)NF * NF];       // 32 MB, [n][k]
__device__ __half g_Xh[(size_t)NF * NF];       // 32 MB, [m][k]

// ---------------- f32x2 helpers --------------------------------------------

__device__ __forceinline__ unsigned long long pk2(float v) {
    unsigned long long r;
    asm("mov.b64 %0, {%1, %1};" : "=l"(r) : "f"(v));
    return r;
}
__device__ __forceinline__ void fma2(unsigned long long& d, unsigned long long a,
                                     unsigned long long b) {
    asm("fma.rn.f32x2 %0, %1, %2, %0;" : "+l"(d) : "l"(a), "l"(b));
}
__device__ __forceinline__ float2 upk(unsigned long long v) {
    float2 f;
    asm("mov.b64 {%0, %1}, %2;" : "=f"(f.x), "=f"(f.y) : "l"(v));
    return f;
}

// ---------------- stage 1: prep kernels ------------------------------------

// fused: blocks [0,256) build T2; blocks [256, 16640) convert x -> fp16
__global__ void k_prep0(const float* __restrict__ c0, const float* __restrict__ c1,
                        const float4* __restrict__ x4) {
    if (blockIdx.x < 256) {
        int idx = blockIdx.x * 256 + threadIdx.x;
        int r2 = idx & 15;
        int q2 = (idx >> 4) & 63;
        int p2 = idx >> 10;
        int a0 = p2 >> 3, a1 = p2 & 7;
        int b0 = q2 >> 3, b1 = q2 & 7;
        float s = 0.f;
#pragma unroll
        for (int r1 = 0; r1 < 16; ++r1)
            s += c0[(a0 * 8 + b0) * 16 + r1] * c1[((r1 * 8 + a1) * 8 + b1) * 16 + r2];
        g_T2[idx] = s;
    } else {
        int idx = (blockIdx.x - 256) * 256 + threadIdx.x;
        float4 v = x4[idx];
        __half2* o = (__half2*)g_Xh;
        o[idx * 2 + 0] = __floats2half2_rn(v.x, v.y);
        o[idx * 2 + 1] = __floats2half2_rn(v.z, v.w);
    }
}

// T3[p3=(p2,a2)][q3=(q2,b2)][r3] = sum_r2 T2[p2,q2,r2] * c2[r2,a2,b2,r3]
// c2 = 16384 floats = 64KB dynamic smem.
#define T3_SMEM (16384 * 4)
__global__ void k_build_T3(const float* __restrict__ c2) {
    extern __shared__ float c2s[];
    __shared__ unsigned long long t2p[16];
    const int tid = threadIdx.x;
    const int p2 = blockIdx.x >> 6, q2 = blockIdx.x & 63;
    for (int i = tid; i < 4096; i += 256)
        *(float4*)(c2s + i * 4) = *(const float4*)(c2 + i * 4);
    if (tid < 16) t2p[tid] = pk2(g_T2[((p2 << 6) + q2) * 16 + tid]);
    __syncthreads();

    const int a2 = tid >> 5, b2 = (tid >> 2) & 7, r3q = tid & 3;
    unsigned long long s0 = 0ull, s1 = 0ull;
#pragma unroll
    for (int r2 = 0; r2 < 16; ++r2) {
        unsigned long long tt = t2p[r2];
        const unsigned long long* cp =
            (const unsigned long long*)&c2s[((r2 * 8 + a2) * 8 + b2) * 16 + r3q * 4];
        fma2(s0, tt, cp[0]);
        fma2(s1, tt, cp[1]);
    }
    float2 f0 = upk(s0), f1 = upk(s1);
    const int p3 = p2 * 8 + a2, q3 = q2 * 8 + b2;
    float4 v;
    v.x = f0.x; v.y = f0.y; v.z = f1.x; v.w = f1.y;
    *(float4*)(g_T3 + ((((size_t)p3 << 9) + q3) << 4) + r3q * 4) = v;
}

// Mt[b=(q3,b3)][a=(p3,a3)] = sum_r3 T3[p3,q3,r3] * c3[r3,a3,b3]
__global__ void k_build_M(const float* __restrict__ c3) {
    __shared__ float c3s[1024];
    for (int i = threadIdx.x; i < 1024; i += 256) c3s[i] = c3[i];
    __syncthreads();

    const int idx = blockIdx.x * 256 + threadIdx.x;   // 512*4096 = 2M
    const int a = idx & (NF - 1);
    const int q3 = idx >> 12;
    const int a3 = a & 7, p3 = a >> 3;

    const float4* t4 = (const float4*)(g_T3 + ((((size_t)p3 << 9) + q3) << 4));
    float t[16];
    *(float4*)(t + 0)  = t4[0];
    *(float4*)(t + 4)  = t4[1];
    *(float4*)(t + 8)  = t4[2];
    *(float4*)(t + 12) = t4[3];

    unsigned long long s0 = 0ull, s1 = 0ull, s2 = 0ull, s3 = 0ull;
#pragma unroll
    for (int r3 = 0; r3 < 16; ++r3) {
        unsigned long long tt = pk2(t[r3]);
        const unsigned long long* cp =
            (const unsigned long long*)&c3s[(r3 * 8 + a3) * 8];
        fma2(s0, tt, cp[0]);
        fma2(s1, tt, cp[1]);
        fma2(s2, tt, cp[2]);
        fma2(s3, tt, cp[3]);
    }
    float2 f0 = upk(s0), f1 = upk(s1), f2 = upk(s2), f3 = upk(s3);
    __half* o = g_Mt + (size_t)(q3 * 8) * NF + a;
    o[0 * NF] = __float2half(f0.x);
    o[1 * NF] = __float2half(f0.y);
    o[2 * NF] = __float2half(f1.x);
    o[3 * NF] = __float2half(f1.y);
    o[4 * NF] = __float2half(f2.x);
    o[5 * NF] = __float2half(f2.y);
    o[6 * NF] = __float2half(f3.x);
    o[7 * NF] = __float2half(f3.y);
}

__global__ void k_nop() {}   // keeps ncu's capture slot aligned on k_gemm

// ---------------- stage 2: fp16 HMMA GEMM ----------------------------------

#define BM 128
#define BN 256
#define BK 64
#define KT (NF / BK)                 // 64
#define A_BYTES (BM * 128)           // 16 KB
#define B_BYTES (BN * 128)           // 32 KB
#define STAGE_BYTES (A_BYTES + B_BYTES)   // 48 KB
#define STAGES 4
#define SMEM_TOTAL (STAGES * STAGE_BYTES) // 192 KB
#define NTHR 512

__device__ __forceinline__ uint32_t sw128(uint32_t off) {
    return off ^ ((off >> 3) & 0x70);
}
__device__ __forceinline__ void cp_async16(uint32_t smem, const void* gmem) {
    asm volatile("cp.async.cg.shared.global [%0], [%1], 16;\n" :: "r"(smem), "l"(gmem));
}
__device__ __forceinline__ void cp_commit() {
    asm volatile("cp.async.commit_group;\n" ::: "memory");
}
__device__ __forceinline__ void ldmatrix_x4(uint32_t* r, uint32_t s) {
    asm volatile("ldmatrix.sync.aligned.m8n8.x4.shared.b16 {%0,%1,%2,%3}, [%4];\n"
                 : "=r"(r[0]), "=r"(r[1]), "=r"(r[2]), "=r"(r[3]) : "r"(s));
}
__device__ __forceinline__ void mma_h_z(uint32_t* d, const uint32_t* a,
                                        const uint32_t* b, uint32_t z) {
    asm volatile("mma.sync.aligned.m16n8k16.row.col.f16.f16.f16.f16 "
                 "{%0,%1}, {%2,%3,%4,%5}, {%6,%7}, {%8,%8};\n"
                 : "=r"(d[0]), "=r"(d[1])
                 : "r"(a[0]), "r"(a[1]), "r"(a[2]), "r"(a[3]),
                   "r"(b[0]), "r"(b[1]), "r"(z));
}
__device__ __forceinline__ void mma_h(uint32_t* d, const uint32_t* a,
                                      const uint32_t* b) {
    asm volatile("mma.sync.aligned.m16n8k16.row.col.f16.f16.f16.f16 "
                 "{%0,%1}, {%2,%3,%4,%5}, {%6,%7}, {%0,%1};\n"
                 : "+r"(d[0]), "+r"(d[1])
                 : "r"(a[0]), "r"(a[1]), "r"(a[2]), "r"(a[3]),
                   "r"(b[0]), "r"(b[1]));
}

__global__ __launch_bounds__(NTHR, 1) void k_gemm(const float* __restrict__ bias,
                                                  float* __restrict__ out) {
    extern __shared__ char smem[];
    uint32_t sb;
    asm("{ .reg .u64 t; cvta.to.shared.u64 t, %1; cvt.u32.u64 %0, t; }"
        : "=r"(sb) : "l"((void*)smem));

    const int tid  = threadIdx.x;
    const int lane = tid & 31;
    const int warp = tid >> 5;      // 0..15
    const int warpM = warp & 3;     // 4 slabs of 32 rows
    const int warpN = warp >> 2;    // 4 slabs of 64 cols
    const int bm = blockIdx.y * BM;
    const int bn = blockIdx.x * BN;

    const __half* Ag = g_Xh;  // [m][k]
    const __half* Bg = g_Mt;  // [n][k]

    float acc[2][8][4];
#pragma unroll
    for (int i = 0; i < 2; i++)
#pragma unroll
        for (int j = 0; j < 8; j++)
#pragma unroll
            for (int k = 0; k < 4; k++) acc[i][j][k] = 0.f;

    uint32_t zero = 0u;

    // Pre-swizzled bases (bits 5-6 clear pre-swizzle); k-slice offset via XOR.
    uint32_t aSw[2];
#pragma unroll
    for (int mi = 0; mi < 2; ++mi) {
        uint32_t off = (uint32_t)(warpM * 32 + mi * 16 + (lane & 15)) * 128
                     + (uint32_t)(lane >> 4) * 16;
        aSw[mi] = sw128(off);
    }
    uint32_t bSw[4];
#pragma unroll
    for (int p = 0; p < 4; ++p) {
        uint32_t row = (uint32_t)(warpN * 64 + p * 16 + ((lane & 16) >> 1) + (lane & 7));
        uint32_t off = row * 128 + (uint32_t)(lane & 8) * 2;
        bSw[p] = sw128(off);
    }

    // stage loader: 3072 x 16B chunks (1024 A + 2048 B), 6 per thread
    auto load_stage = [&](int s, int kt) {
        const int kk = kt * BK;
        const uint32_t base = sb + (uint32_t)s * STAGE_BYTES;
#pragma unroll
        for (int i = 0; i < 6; ++i) {
            int cid = tid + i * NTHR;
            if (cid < 1024) {                       // A: 128 rows x 8 chunks
                int r = cid >> 3, c = cid & 7;
                cp_async16(base + sw128((uint32_t)(r * 128 + c * 16)),
                           Ag + (size_t)(bm + r) * NF + kk + c * 8);
            } else {                                // B: 256 rows x 8 chunks
                int cid2 = cid - 1024;
                int r = cid2 >> 3, c = cid2 & 7;
                cp_async16(base + A_BYTES + sw128((uint32_t)(r * 128 + c * 16)),
                           Bg + (size_t)(bn + r) * NF + kk + c * 8);
            }
        }
        cp_commit();
    };

    load_stage(0, 0);
    load_stage(1, 1);
    load_stage(2, 2);

    for (int kt = 0; kt < KT; ++kt) {
        asm volatile("cp.async.wait_group 2;\n" ::: "memory");
        __syncthreads();
        if (kt + 3 < KT) load_stage((kt + 3) & 3, kt + 3);
        else cp_commit();

        const uint32_t stA = sb + (uint32_t)(kt & 3) * STAGE_BYTES;
        const uint32_t stB = stA + A_BYTES;

        // All A fragments for both 16-row bands up front: 8 ldmatrix.
        uint32_t af[2][4][4];
#pragma unroll
        for (int mi = 0; mi < 2; ++mi)
#pragma unroll
            for (int k = 0; k < 4; ++k)
                ldmatrix_x4(af[mi][k], stA + (aSw[mi] ^ ((uint32_t)k << 5)));

#pragma unroll
        for (int p = 0; p < 4; ++p) {
            // Each B fragment loaded exactly once: 4 ldmatrix per p.
            uint32_t bf[4][4];
#pragma unroll
            for (int k = 0; k < 4; ++k)
                ldmatrix_x4(bf[k], stB + (bSw[p] ^ ((uint32_t)k << 5)));

            // 4 chains (mi x h) advance in LOCKSTEP: per-chain RAW separated
            // by 3 independent mmas -> latency hidden by in-warp ILP.
            uint32_t c2[2][2][2];
#pragma unroll
            for (int mi = 0; mi < 2; ++mi)
#pragma unroll
                for (int h = 0; h < 2; ++h)
                    mma_h_z(c2[mi][h], af[mi][0], &bf[0][h * 2], zero);
#pragma unroll
            for (int s = 1; s < 4; ++s)
#pragma unroll
                for (int mi = 0; mi < 2; ++mi)
#pragma unroll
                    for (int h = 0; h < 2; ++h)
                        mma_h(c2[mi][h], af[mi][s], &bf[s][h * 2]);

            // promote all 4 chains
#pragma unroll
            for (int mi = 0; mi < 2; ++mi)
#pragma unroll
                for (int h = 0; h < 2; ++h) {
                    const int ni = p * 2 + h;
                    float2 f0 = __half22float2(*reinterpret_cast<__half2*>(&c2[mi][h][0]));
                    float2 f1 = __half22float2(*reinterpret_cast<__half2*>(&c2[mi][h][1]));
                    acc[mi][ni][0] += f0.x;
                    acc[mi][ni][1] += f0.y;
                    acc[mi][ni][2] += f1.x;
                    acc[mi][ni][3] += f1.y;
                }
        }
    }

    // epilogue: relu(acc + bias), fp32 out
#pragma unroll
    for (int mi = 0; mi < 2; ++mi) {
#pragma unroll
        for (int ni = 0; ni < 8; ++ni) {
            int row = bm + warpM * 32 + mi * 16 + (lane >> 2);
            int col = bn + warpN * 64 + ni * 8 + (lane & 3) * 2;
            float b0 = __ldg(bias + col), b1 = __ldg(bias + col + 1);
            float2 v0, v1;
            v0.x = fmaxf(acc[mi][ni][0] + b0, 0.f);
            v0.y = fmaxf(acc[mi][ni][1] + b1, 0.f);
            v1.x = fmaxf(acc[mi][ni][2] + b0, 0.f);
            v1.y = fmaxf(acc[mi][ni][3] + b1, 0.f);
            *(float2*)(out + (size_t)row * NF + col) = v0;
            *(float2*)(out + (size_t)(row + 8) * NF + col) = v1;
        }
    }
}

// ---------------------------------------------------------------------------

extern "C" void kernel_launch(void* const* d_in, const int* in_sizes, int n_in,
                              void* d_out, int out_size) {
    const float* x  = (const float*)d_in[0];
    const float* c0 = (const float*)d_in[1];
    const float* c1 = (const float*)d_in[2];
    const float* c2 = (const float*)d_in[3];
    const float* c3 = (const float*)d_in[4];
    const float* bv = (const float*)d_in[5];
    float* out = (float*)d_out;

    static bool attr_done = false;
    if (!attr_done) {
        cudaFuncSetAttribute(k_gemm, cudaFuncAttributeMaxDynamicSharedMemorySize,
                             SMEM_TOTAL);
        cudaFuncSetAttribute(k_build_T3, cudaFuncAttributeMaxDynamicSharedMemorySize,
                             T3_SMEM);
        attr_done = true;
    }

    k_prep0<<<16640, 256>>>(c0, c1, (const float4*)x);   // T2 + x->fp16
    k_build_T3<<<4096, 256, T3_SMEM>>>(c2);
    k_build_M<<<8192, 256>>>(c3);

    dim3 grid(NF / BN, NF / BM);  // (16, 32)
    k_gemm<<<grid, NTHR, SMEM_TOTAL>>>(bv, out);
    k_nop<<<1, 32>>>();
}